// round 11
// baseline (speedup 1.0000x reference)
#include <cuda_runtime.h>

#define D 4096
#define NV4 (D / 4)        // 1024 float4 per row
#define THREADS 128
#define EPS 1e-6f

// Streaming load with 256B L2 prefetch: coarsens DRAM read bursts on a
// fully-contiguous stream (neighbor line is consumed by the adjacent warp).
__device__ __forceinline__ float4 ldcs256(const float4* p)
{
    float4 v;
    asm volatile("ld.global.cs.L2::256B.v4.f32 {%0,%1,%2,%3}, [%4];"
                 : "=f"(v.x), "=f"(v.y), "=f"(v.z), "=f"(v.w)
                 : "l"(p));
    return v;
}

__global__ __launch_bounds__(THREADS, 10) void mrmsnorm_kernel(
    const float4* __restrict__ x,
    const float4* __restrict__ scale,
    float4* __restrict__ out)
{
    __shared__ float ws[4][4];   // [warp][seg-group]

    const int t = threadIdx.x;
    const int warp = t >> 5;
    const int lane = t & 31;

    const size_t row = blockIdx.x;
    const float4* __restrict__ xr = x + row * NV4;
    float4* __restrict__ orow = out + row * NV4;

    // Front-issue all 8 streaming loads: slice j covers f4 idx [128j, 128j+128).
    float4 v0 = ldcs256(&xr[t]);
    float4 v1 = ldcs256(&xr[t + 1 * THREADS]);
    float4 v2 = ldcs256(&xr[t + 2 * THREADS]);
    float4 v3 = ldcs256(&xr[t + 3 * THREADS]);
    float4 v4 = ldcs256(&xr[t + 4 * THREADS]);
    float4 v5 = ldcs256(&xr[t + 5 * THREADS]);
    float4 v6 = ldcs256(&xr[t + 6 * THREADS]);
    float4 v7 = ldcs256(&xr[t + 7 * THREADS]);

    // Per-thread partials grouped by segment:
    //   p0: slice0 -> seg0/seg1 (split at t==64, warp-aligned)
    //   p1: slice1 -> seg2 [128,256)
    //   p2: slices2-3 -> seg3 [256,512)
    //   p3: slices4-7 -> seg4 [512,1024)
    float p0 = v0.x * v0.x + v0.y * v0.y + v0.z * v0.z + v0.w * v0.w;
    float p1 = v1.x * v1.x + v1.y * v1.y + v1.z * v1.z + v1.w * v1.w;
    float p2 = v2.x * v2.x + v2.y * v2.y + v2.z * v2.z + v2.w * v2.w
             + v3.x * v3.x + v3.y * v3.y + v3.z * v3.z + v3.w * v3.w;
    float p3 = v4.x * v4.x + v4.y * v4.y + v4.z * v4.z + v4.w * v4.w
             + v5.x * v5.x + v5.y * v5.y + v5.z * v5.z + v5.w * v5.w
             + v6.x * v6.x + v6.y * v6.y + v6.z * v6.z + v6.w * v6.w
             + v7.x * v7.x + v7.y * v7.y + v7.z * v7.z + v7.w * v7.w;

    #pragma unroll
    for (int o = 16; o > 0; o >>= 1) {
        p0 += __shfl_down_sync(0xffffffffu, p0, o);
        p1 += __shfl_down_sync(0xffffffffu, p1, o);
        p2 += __shfl_down_sync(0xffffffffu, p2, o);
        p3 += __shfl_down_sync(0xffffffffu, p3, o);
    }

    if (lane == 0) {
        ws[warp][0] = p0;
        ws[warp][1] = p1;
        ws[warp][2] = p2;
        ws[warp][3] = p3;
    }
    __syncthreads();

    // seg0 [0,64): warps 0-1 of slice0; seg1 [64,128): warps 2-3 of slice0.
    float seg0 = ws[0][0] + ws[1][0];
    float seg1 = ws[2][0] + ws[3][0];
    float seg2 = ws[0][1] + ws[1][1] + ws[2][1] + ws[3][1];
    float seg3 = ws[0][2] + ws[1][2] + ws[2][2] + ws[3][2];
    float seg4 = ws[0][3] + ws[1][3] + ws[2][3] + ws[3][3];

    float c0 = seg0;
    float c1 = c0 + seg1;
    float c2 = c1 + seg2;
    float c3 = c2 + seg3;
    float c4 = c3 + seg4;

    float r0 = rsqrtf(c0 * (1.0f / 256.0f)  + EPS);
    float r1 = rsqrtf(c1 * (1.0f / 512.0f)  + EPS);
    float r2 = rsqrtf(c2 * (1.0f / 1024.0f) + EPS);
    float r3 = rsqrtf(c3 * (1.0f / 2048.0f) + EPS);
    float r4 = rsqrtf(c4 * (1.0f / 4096.0f) + EPS);

    float r01 = (t < 64) ? r0 : r1;   // warp-uniform select for slice0

    {
        float4 s = __ldg(&scale[t]);
        float4 o;
        o.x = v0.x * r01 * s.x;  o.y = v0.y * r01 * s.y;
        o.z = v0.z * r01 * s.z;  o.w = v0.w * r01 * s.w;
        __stcs(&orow[t], o);
    }
    {
        float4 s = __ldg(&scale[t + 1 * THREADS]);
        float4 o;
        o.x = v1.x * r2 * s.x;  o.y = v1.y * r2 * s.y;
        o.z = v1.z * r2 * s.z;  o.w = v1.w * r2 * s.w;
        __stcs(&orow[t + 1 * THREADS], o);
    }
    {
        float4 s = __ldg(&scale[t + 2 * THREADS]);
        float4 o;
        o.x = v2.x * r3 * s.x;  o.y = v2.y * r3 * s.y;
        o.z = v2.z * r3 * s.z;  o.w = v2.w * r3 * s.w;
        __stcs(&orow[t + 2 * THREADS], o);
    }
    {
        float4 s = __ldg(&scale[t + 3 * THREADS]);
        float4 o;
        o.x = v3.x * r3 * s.x;  o.y = v3.y * r3 * s.y;
        o.z = v3.z * r3 * s.z;  o.w = v3.w * r3 * s.w;
        __stcs(&orow[t + 3 * THREADS], o);
    }
    {
        float4 s = __ldg(&scale[t + 4 * THREADS]);
        float4 o;
        o.x = v4.x * r4 * s.x;  o.y = v4.y * r4 * s.y;
        o.z = v4.z * r4 * s.z;  o.w = v4.w * r4 * s.w;
        __stcs(&orow[t + 4 * THREADS], o);
    }
    {
        float4 s = __ldg(&scale[t + 5 * THREADS]);
        float4 o;
        o.x = v5.x * r4 * s.x;  o.y = v5.y * r4 * s.y;
        o.z = v5.z * r4 * s.z;  o.w = v5.w * r4 * s.w;
        __stcs(&orow[t + 5 * THREADS], o);
    }
    {
        float4 s = __ldg(&scale[t + 6 * THREADS]);
        float4 o;
        o.x = v6.x * r4 * s.x;  o.y = v6.y * r4 * s.y;
        o.z = v6.z * r4 * s.z;  o.w = v6.w * r4 * s.w;
        __stcs(&orow[t + 6 * THREADS], o);
    }
    {
        float4 s = __ldg(&scale[t + 7 * THREADS]);
        float4 o;
        o.x = v7.x * r4 * s.x;  o.y = v7.y * r4 * s.y;
        o.z = v7.z * r4 * s.z;  o.w = v7.w * r4 * s.w;
        __stcs(&orow[t + 7 * THREADS], o);
    }
}

extern "C" void kernel_launch(void* const* d_in, const int* in_sizes, int n_in,
                              void* d_out, int out_size)
{
    const float4* x = (const float4*)d_in[0];
    const float4* scale = (const float4*)d_in[1];
    float4* out = (float4*)d_out;

    const int rows = out_size / D;   // 16384
    mrmsnorm_kernel<<<rows, THREADS>>>(x, scale, out);
}

// round 12
// speedup vs baseline: 1.0031x; 1.0031x over previous
#include <cuda_runtime.h>

#define D 4096
#define NV4 (D / 4)        // 1024 float4 per row
#define THREADS 128
#define EPS 1e-6f

__global__ __launch_bounds__(THREADS) void mrmsnorm_kernel(
    const float4* __restrict__ x,
    const float4* __restrict__ scale,
    float4* __restrict__ out)
{
    __shared__ float ws[4][4];   // [warp][seg-group]

    const int t = threadIdx.x;
    const int warp = t >> 5;
    const int lane = t & 31;

    const size_t row = blockIdx.x;
    const float4* __restrict__ xr = x + row * NV4;
    float4* __restrict__ orow = out + row * NV4;

    // Front-issue all 8 streaming loads: slice j covers f4 idx [128j, 128j+128).
    float4 v0 = __ldcs(&xr[t]);
    float4 v1 = __ldcs(&xr[t + 1 * THREADS]);
    float4 v2 = __ldcs(&xr[t + 2 * THREADS]);
    float4 v3 = __ldcs(&xr[t + 3 * THREADS]);
    float4 v4 = __ldcs(&xr[t + 4 * THREADS]);
    float4 v5 = __ldcs(&xr[t + 5 * THREADS]);
    float4 v6 = __ldcs(&xr[t + 6 * THREADS]);
    float4 v7 = __ldcs(&xr[t + 7 * THREADS]);

    // Per-thread partials grouped by segment:
    //   p0: slice0 -> seg0/seg1 (split at t==64, warp-aligned)
    //   p1: slice1 -> seg2 [128,256)
    //   p2: slices2-3 -> seg3 [256,512)
    //   p3: slices4-7 -> seg4 [512,1024)
    float p0 = v0.x * v0.x + v0.y * v0.y + v0.z * v0.z + v0.w * v0.w;
    float p1 = v1.x * v1.x + v1.y * v1.y + v1.z * v1.z + v1.w * v1.w;
    float p2 = v2.x * v2.x + v2.y * v2.y + v2.z * v2.z + v2.w * v2.w
             + v3.x * v3.x + v3.y * v3.y + v3.z * v3.z + v3.w * v3.w;
    float p3 = v4.x * v4.x + v4.y * v4.y + v4.z * v4.z + v4.w * v4.w
             + v5.x * v5.x + v5.y * v5.y + v5.z * v5.z + v5.w * v5.w
             + v6.x * v6.x + v6.y * v6.y + v6.z * v6.z + v6.w * v6.w
             + v7.x * v7.x + v7.y * v7.y + v7.z * v7.z + v7.w * v7.w;

    #pragma unroll
    for (int o = 16; o > 0; o >>= 1) {
        p0 += __shfl_down_sync(0xffffffffu, p0, o);
        p1 += __shfl_down_sync(0xffffffffu, p1, o);
        p2 += __shfl_down_sync(0xffffffffu, p2, o);
        p3 += __shfl_down_sync(0xffffffffu, p3, o);
    }

    if (lane == 0) {
        ws[warp][0] = p0;
        ws[warp][1] = p1;
        ws[warp][2] = p2;
        ws[warp][3] = p3;
    }
    __syncthreads();

    // Hoist scale loads (L1-resident after first CTA) so their latency
    // overlaps the dependent rsqrt chain below instead of the store phase.
    float4 s0 = __ldg(&scale[t]);
    float4 s1 = __ldg(&scale[t + 1 * THREADS]);
    float4 s2 = __ldg(&scale[t + 2 * THREADS]);
    float4 s3 = __ldg(&scale[t + 3 * THREADS]);
    float4 s4 = __ldg(&scale[t + 4 * THREADS]);
    float4 s5 = __ldg(&scale[t + 5 * THREADS]);
    float4 s6 = __ldg(&scale[t + 6 * THREADS]);
    float4 s7 = __ldg(&scale[t + 7 * THREADS]);

    // seg0 [0,64): warps 0-1 of slice0; seg1 [64,128): warps 2-3 of slice0.
    float seg0 = ws[0][0] + ws[1][0];
    float seg1 = ws[2][0] + ws[3][0];
    float seg2 = ws[0][1] + ws[1][1] + ws[2][1] + ws[3][1];
    float seg3 = ws[0][2] + ws[1][2] + ws[2][2] + ws[3][2];
    float seg4 = ws[0][3] + ws[1][3] + ws[2][3] + ws[3][3];

    float c0 = seg0;
    float c1 = c0 + seg1;
    float c2 = c1 + seg2;
    float c3 = c2 + seg3;
    float c4 = c3 + seg4;

    float r0 = rsqrtf(c0 * (1.0f / 256.0f)  + EPS);
    float r1 = rsqrtf(c1 * (1.0f / 512.0f)  + EPS);
    float r2 = rsqrtf(c2 * (1.0f / 1024.0f) + EPS);
    float r3 = rsqrtf(c3 * (1.0f / 2048.0f) + EPS);
    float r4 = rsqrtf(c4 * (1.0f / 4096.0f) + EPS);

    float r01 = (t < 64) ? r0 : r1;   // warp-uniform select for slice0

    {
        float4 o;
        o.x = v0.x * r01 * s0.x;  o.y = v0.y * r01 * s0.y;
        o.z = v0.z * r01 * s0.z;  o.w = v0.w * r01 * s0.w;
        __stcs(&orow[t], o);
    }
    {
        float4 o;
        o.x = v1.x * r2 * s1.x;  o.y = v1.y * r2 * s1.y;
        o.z = v1.z * r2 * s1.z;  o.w = v1.w * r2 * s1.w;
        __stcs(&orow[t + 1 * THREADS], o);
    }
    {
        float4 o;
        o.x = v2.x * r3 * s2.x;  o.y = v2.y * r3 * s2.y;
        o.z = v2.z * r3 * s2.z;  o.w = v2.w * r3 * s2.w;
        __stcs(&orow[t + 2 * THREADS], o);
    }
    {
        float4 o;
        o.x = v3.x * r3 * s3.x;  o.y = v3.y * r3 * s3.y;
        o.z = v3.z * r3 * s3.z;  o.w = v3.w * r3 * s3.w;
        __stcs(&orow[t + 3 * THREADS], o);
    }
    {
        float4 o;
        o.x = v4.x * r4 * s4.x;  o.y = v4.y * r4 * s4.y;
        o.z = v4.z * r4 * s4.z;  o.w = v4.w * r4 * s4.w;
        __stcs(&orow[t + 4 * THREADS], o);
    }
    {
        float4 o;
        o.x = v5.x * r4 * s5.x;  o.y = v5.y * r4 * s5.y;
        o.z = v5.z * r4 * s5.z;  o.w = v5.w * r4 * s5.w;
        __stcs(&orow[t + 5 * THREADS], o);
    }
    {
        float4 o;
        o.x = v6.x * r4 * s6.x;  o.y = v6.y * r4 * s6.y;
        o.z = v6.z * r4 * s6.z;  o.w = v6.w * r4 * s6.w;
        __stcs(&orow[t + 6 * THREADS], o);
    }
    {
        float4 o;
        o.x = v7.x * r4 * s7.x;  o.y = v7.y * r4 * s7.y;
        o.z = v7.z * r4 * s7.z;  o.w = v7.w * r4 * s7.w;
        __stcs(&orow[t + 7 * THREADS], o);
    }
}

extern "C" void kernel_launch(void* const* d_in, const int* in_sizes, int n_in,
                              void* d_out, int out_size)
{
    const float4* x = (const float4*)d_in[0];
    const float4* scale = (const float4*)d_in[1];
    float4* out = (float4*)d_out;

    const int rows = out_size / D;   // 16384
    mrmsnorm_kernel<<<rows, THREADS>>>(x, scale, out);
}

// round 13
// speedup vs baseline: 1.0066x; 1.0035x over previous
#include <cuda_runtime.h>

#define D 4096
#define NV4 (D / 4)        // 1024 float4 per row
#define THREADS 128
#define EPS 1e-6f

__global__ __launch_bounds__(THREADS) void mrmsnorm_kernel(
    const float4* __restrict__ x,
    const float4* __restrict__ scale,
    float4* __restrict__ out)
{
    __shared__ float ws[4][4];   // [warp][seg-group]

    const int t = threadIdx.x;
    const int warp = t >> 5;
    const int lane = t & 31;

    const size_t row = blockIdx.x;
    const float4* __restrict__ xr = x + row * NV4;
    float4* __restrict__ orow = out + row * NV4;

    // Front-issue all 8 streaming loads: slice j covers f4 idx [128j, 128j+128).
    float4 v0 = __ldcs(&xr[t]);
    float4 v1 = __ldcs(&xr[t + 1 * THREADS]);
    float4 v2 = __ldcs(&xr[t + 2 * THREADS]);
    float4 v3 = __ldcs(&xr[t + 3 * THREADS]);
    float4 v4 = __ldcs(&xr[t + 4 * THREADS]);
    float4 v5 = __ldcs(&xr[t + 5 * THREADS]);
    float4 v6 = __ldcs(&xr[t + 6 * THREADS]);
    float4 v7 = __ldcs(&xr[t + 7 * THREADS]);

    // Per-thread partials grouped by segment:
    //   p0: slice0 -> seg0/seg1 (split at t==64, warp-aligned)
    //   p1: slice1 -> seg2 [128,256)
    //   p2: slices2-3 -> seg3 [256,512)
    //   p3: slices4-7 -> seg4 [512,1024)
    float p0 = v0.x * v0.x + v0.y * v0.y + v0.z * v0.z + v0.w * v0.w;
    float p1 = v1.x * v1.x + v1.y * v1.y + v1.z * v1.z + v1.w * v1.w;
    float p2 = v2.x * v2.x + v2.y * v2.y + v2.z * v2.z + v2.w * v2.w
             + v3.x * v3.x + v3.y * v3.y + v3.z * v3.z + v3.w * v3.w;
    float p3 = v4.x * v4.x + v4.y * v4.y + v4.z * v4.z + v4.w * v4.w
             + v5.x * v5.x + v5.y * v5.y + v5.z * v5.z + v5.w * v5.w
             + v6.x * v6.x + v6.y * v6.y + v6.z * v6.z + v6.w * v6.w
             + v7.x * v7.x + v7.y * v7.y + v7.z * v7.z + v7.w * v7.w;

    #pragma unroll
    for (int o = 16; o > 0; o >>= 1) {
        p0 += __shfl_down_sync(0xffffffffu, p0, o);
        p1 += __shfl_down_sync(0xffffffffu, p1, o);
        p2 += __shfl_down_sync(0xffffffffu, p2, o);
        p3 += __shfl_down_sync(0xffffffffu, p3, o);
    }

    if (lane == 0) {
        ws[warp][0] = p0;
        ws[warp][1] = p1;
        ws[warp][2] = p2;
        ws[warp][3] = p3;
    }
    __syncthreads();

    // seg0 [0,64): warps 0-1 of slice0; seg1 [64,128): warps 2-3 of slice0.
    float seg0 = ws[0][0] + ws[1][0];
    float seg1 = ws[2][0] + ws[3][0];
    float seg2 = ws[0][1] + ws[1][1] + ws[2][1] + ws[3][1];
    float seg3 = ws[0][2] + ws[1][2] + ws[2][2] + ws[3][2];
    float seg4 = ws[0][3] + ws[1][3] + ws[2][3] + ws[3][3];

    float c0 = seg0;
    float c1 = c0 + seg1;
    float c2 = c1 + seg2;
    float c3 = c2 + seg3;
    float c4 = c3 + seg4;

    float r0 = rsqrtf(c0 * (1.0f / 256.0f)  + EPS);
    float r1 = rsqrtf(c1 * (1.0f / 512.0f)  + EPS);
    float r2 = rsqrtf(c2 * (1.0f / 1024.0f) + EPS);
    float r3 = rsqrtf(c3 * (1.0f / 2048.0f) + EPS);
    float r4 = rsqrtf(c4 * (1.0f / 4096.0f) + EPS);

    float r01 = (t < 64) ? r0 : r1;   // warp-uniform select for slice0

    {
        float4 s = __ldg(&scale[t]);
        float4 o;
        o.x = v0.x * r01 * s.x;  o.y = v0.y * r01 * s.y;
        o.z = v0.z * r01 * s.z;  o.w = v0.w * r01 * s.w;
        __stcs(&orow[t], o);
    }
    {
        float4 s = __ldg(&scale[t + 1 * THREADS]);
        float4 o;
        o.x = v1.x * r2 * s.x;  o.y = v1.y * r2 * s.y;
        o.z = v1.z * r2 * s.z;  o.w = v1.w * r2 * s.w;
        __stcs(&orow[t + 1 * THREADS], o);
    }
    {
        float4 s = __ldg(&scale[t + 2 * THREADS]);
        float4 o;
        o.x = v2.x * r3 * s.x;  o.y = v2.y * r3 * s.y;
        o.z = v2.z * r3 * s.z;  o.w = v2.w * r3 * s.w;
        __stcs(&orow[t + 2 * THREADS], o);
    }
    {
        float4 s = __ldg(&scale[t + 3 * THREADS]);
        float4 o;
        o.x = v3.x * r3 * s.x;  o.y = v3.y * r3 * s.y;
        o.z = v3.z * r3 * s.z;  o.w = v3.w * r3 * s.w;
        __stcs(&orow[t + 3 * THREADS], o);
    }
    {
        float4 s = __ldg(&scale[t + 4 * THREADS]);
        float4 o;
        o.x = v4.x * r4 * s.x;  o.y = v4.y * r4 * s.y;
        o.z = v4.z * r4 * s.z;  o.w = v4.w * r4 * s.w;
        __stcs(&orow[t + 4 * THREADS], o);
    }
    {
        float4 s = __ldg(&scale[t + 5 * THREADS]);
        float4 o;
        o.x = v5.x * r4 * s.x;  o.y = v5.y * r4 * s.y;
        o.z = v5.z * r4 * s.z;  o.w = v5.w * r4 * s.w;
        __stcs(&orow[t + 5 * THREADS], o);
    }
    {
        float4 s = __ldg(&scale[t + 6 * THREADS]);
        float4 o;
        o.x = v6.x * r4 * s.x;  o.y = v6.y * r4 * s.y;
        o.z = v6.z * r4 * s.z;  o.w = v6.w * r4 * s.w;
        __stcs(&orow[t + 6 * THREADS], o);
    }
    {
        float4 s = __ldg(&scale[t + 7 * THREADS]);
        float4 o;
        o.x = v7.x * r4 * s.x;  o.y = v7.y * r4 * s.y;
        o.z = v7.z * r4 * s.z;  o.w = v7.w * r4 * s.w;
        __stcs(&orow[t + 7 * THREADS], o);
    }
}

extern "C" void kernel_launch(void* const* d_in, const int* in_sizes, int n_in,
                              void* d_out, int out_size)
{
    const float4* x = (const float4*)d_in[0];
    const float4* scale = (const float4*)d_in[1];
    float4* out = (float4*)d_out;

    const int rows = out_size / D;   // 16384
    mrmsnorm_kernel<<<rows, THREADS>>>(x, scale, out);
}